// round 15
// baseline (speedup 1.0000x reference)
#include <cuda_runtime.h>
#include <cuda_bf16.h>
#include <math.h>
#include <stdint.h>

// Problem constants
#define BB 64
#define TT 512
#define DD 512
#define HH 8
#define DHH 64

// ---------------- scratch (device globals; allocation-free) ----------------
__device__ float g_qin[BB * TT * DD];
__device__ float g_kin[BB * TT * DD];
__device__ float g_qp [BB * TT * DD];
__device__ float g_kp [BB * TT * DD];
__device__ float g_vp [BB * TT * DD];
__device__ float g_res[BB * TT * DD];
__device__ float g_hid[BB * TT * 4 * DD];
__device__ float g_res2[BB * TT * DD];
// tf32-rounded weight copies
__device__ float g_wq[DD * DD];
__device__ float g_wk[DD * DD];
__device__ float g_wv[DD * DD];
__device__ float g_f1[DD * 4 * DD];
__device__ float g_f2[4 * DD * DD];

__device__ __forceinline__ uint32_t f2tf32(float x) {
    uint32_t r;
    asm("cvt.rna.tf32.f32 %0, %1;" : "=r"(r) : "f"(x));
    return r;
}
__device__ __forceinline__ float tf32r(float x) {
    return __uint_as_float(f2tf32(x));
}

#define CPASYNC16(dst, src) \
    asm volatile("cp.async.cg.shared.global [%0], [%1], 16;" :: "r"(dst), "l"(src))

// ---------------- kernel 0: round all weights to tf32 (single launch) ----------------
__global__ void roundw_all_kernel(const float* __restrict__ wq0, float* __restrict__ wq1,
                                  const float* __restrict__ wk0, float* __restrict__ wk1,
                                  const float* __restrict__ wv0, float* __restrict__ wv1,
                                  const float* __restrict__ f10, float* __restrict__ f11,
                                  const float* __restrict__ f20, float* __restrict__ f21) {
    int i = blockIdx.x * blockDim.x + threadIdx.x;
    if (i < DD * DD) {
        wq1[i] = tf32r(wq0[i]);
        wk1[i] = tf32r(wk0[i]);
        wv1[i] = tf32r(wv0[i]);
    }
    if (i < DD * 4 * DD) {
        f11[i] = tf32r(f10[i]);
        f21[i] = tf32r(f20[i]);
    }
}

// ---------------- kernel 1: positional encoding add (tf32-rounded out) ----------------
__global__ void addpe_kernel(const float* __restrict__ q, const float* __restrict__ k,
                             float* __restrict__ qo, float* __restrict__ ko) {
    int idx = blockIdx.x * blockDim.x + threadIdx.x;
    if (idx >= BB * TT * DD) return;
    int d = idx % DD;
    int t = (idx / DD) % TT;
    int j = (d < DD / 2) ? d : d - DD / 2;
    float invf = expf(-(2.0f * (float)j / (float)DD) * 9.210340371976184f); // ln(10000)
    float arg = (float)t * invf;
    float pe = (d < DD / 2) ? cosf(arg) : sinf(arg);
    qo[idx] = tf32r(q[idx] + pe);
    ko[idx] = tf32r(k[idx] + pe);
}

// ---------------- TF32 GEMM v8: software-pipelined fragments ----------------
// 128x128 block, 64x32 warp tile, 2 CTAs/SM, 3-stage cp.async, 1 barrier/K-tile.
// A-fragment LDSM for slice ks+1 issued right after its consumer HMMAs of slice ks;
// B-fragment LDS double-buffered 2 slices ahead. Register-neutral.
template<bool RELU, bool ADD, bool TFOUT>
__global__ __launch_bounds__(256, 2) void tf32_gemm_v8(
        const float* __restrict__ A, const float* __restrict__ W,
        const float* __restrict__ Src, float* __restrict__ C,
        int M, int N, int K) {
    const int BK = 32;
    const int AST = 36, BST = 136;            // u32 strides; both conflict-free
    const int ASTAGE = 128 * AST, BSTAGE = 32 * BST;
    const int STAGE = ASTAGE + BSTAGE;        // 8960 u32 per stage
    extern __shared__ uint32_t sm[];

    int tid = threadIdx.x;
    int lane = tid & 31, warp = tid >> 5;
    int wr = (warp >> 2) * 64;                // 2 warp-rows
    int wc = (warp & 3) * 32;                 // 4 warp-cols
    int bm = blockIdx.y * 128, bn = blockIdx.x * 128;
    int g = lane >> 2, q = lane & 3;

    uint32_t smem_base = (uint32_t)__cvta_generic_to_shared(sm);

    int lrow = ((lane >> 3) & 1) * 8 + (lane & 7);
    int lcol = (lane >> 4) * 4;

    float acc[4][4][4];
    #pragma unroll
    for (int mi = 0; mi < 4; mi++)
        #pragma unroll
        for (int ni = 0; ni < 4; ni++)
            #pragma unroll
            for (int r = 0; r < 4; r++) acc[mi][ni][r] = 0.0f;

    auto stage_load = [&](int k0, int s) {
        uint32_t abase = smem_base + (uint32_t)(s * STAGE) * 4u;
        uint32_t bbase = abase + (uint32_t)ASTAGE * 4u;
        #pragma unroll
        for (int i = 0; i < 4; i++) {
            int c = tid + i * 256;
            int row = c >> 3, col = (c & 7) * 4;
            CPASYNC16(abase + (uint32_t)(row * AST + col) * 4u,
                      A + (size_t)(bm + row) * K + k0 + col);
        }
        #pragma unroll
        for (int i = 0; i < 4; i++) {
            int c = tid + i * 256;
            int kr = c >> 5, col = (c & 31) * 4;
            CPASYNC16(bbase + (uint32_t)(kr * BST + col) * 4u,
                      W + (size_t)(k0 + kr) * N + bn + col);
        }
        asm volatile("cp.async.commit_group;");
    };

    int nk = K / BK;
    stage_load(0, 0);
    stage_load(BK, 1);

    for (int it = 0; it < nk; it++) {
        asm volatile("cp.async.wait_group 1;");
        __syncthreads();   // stage it%3 visible to all; all warps done with it-1
        if (it + 2 < nk) stage_load((it + 2) * BK, (it + 2) % 3);
        else asm volatile("cp.async.commit_group;");

        int s = it % 3;
        uint32_t abuf = smem_base + (uint32_t)(s * STAGE) * 4u;
        const uint32_t* Bb = sm + s * STAGE + ASTAGE;

        // tile prologue: A frags for slice 0, B frags for slices 0 and 1
        uint32_t af[4][4];
        #pragma unroll
        for (int mi = 0; mi < 4; mi++) {
            uint32_t addr = abuf + (uint32_t)((wr + mi * 16 + lrow) * AST + lcol) * 4u;
            asm volatile(
                "ldmatrix.sync.aligned.m8n8.x4.shared.b16 {%0,%1,%2,%3}, [%4];"
                : "=r"(af[mi][0]), "=r"(af[mi][1]), "=r"(af[mi][2]), "=r"(af[mi][3])
                : "r"(addr));
        }
        uint32_t bf[2][4][2];
        #pragma unroll
        for (int ni = 0; ni < 4; ni++) {
            int cn = wc + ni * 8 + g;
            bf[0][ni][0] = Bb[(q) * BST + cn];
            bf[0][ni][1] = Bb[(4 + q) * BST + cn];
            bf[1][ni][0] = Bb[(8 + q) * BST + cn];
            bf[1][ni][1] = Bb[(12 + q) * BST + cn];
        }

        #pragma unroll
        for (int ks = 0; ks < 4; ks++) {
            int slot = ks & 1;
            #pragma unroll
            for (int mi = 0; mi < 4; mi++) {
                #pragma unroll
                for (int ni = 0; ni < 4; ni++) {
                    asm volatile(
                        "mma.sync.aligned.m16n8k8.row.col.f32.tf32.tf32.f32 "
                        "{%0,%1,%2,%3},{%4,%5,%6,%7},{%8,%9},{%0,%1,%2,%3};"
                        : "+f"(acc[mi][ni][0]), "+f"(acc[mi][ni][1]),
                          "+f"(acc[mi][ni][2]), "+f"(acc[mi][ni][3])
                        : "r"(af[mi][0]), "r"(af[mi][1]), "r"(af[mi][2]), "r"(af[mi][3]),
                          "r"(bf[slot][ni][0]), "r"(bf[slot][ni][1]));
                }
                if (ks < 3) {
                    // reload af[mi] for slice ks+1 right after its last consumer
                    int kk = (ks + 1) * 8;
                    uint32_t addr = abuf +
                        (uint32_t)((wr + mi * 16 + lrow) * AST + kk + lcol) * 4u;
                    asm volatile(
                        "ldmatrix.sync.aligned.m8n8.x4.shared.b16 {%0,%1,%2,%3}, [%4];"
                        : "=r"(af[mi][0]), "=r"(af[mi][1]),
                          "=r"(af[mi][2]), "=r"(af[mi][3])
                        : "r"(addr));
                }
            }
            if (ks < 2) {
                // reload bf[slot] for slice ks+2 after all its consumers
                int kk = (ks + 2) * 8;
                #pragma unroll
                for (int ni = 0; ni < 4; ni++) {
                    int cn = wc + ni * 8 + g;
                    bf[slot][ni][0] = Bb[(kk + q) * BST + cn];
                    bf[slot][ni][1] = Bb[(kk + 4 + q) * BST + cn];
                }
            }
        }
    }

    #pragma unroll
    for (int mi = 0; mi < 4; mi++) {
        #pragma unroll
        for (int ni = 0; ni < 4; ni++) {
            int r0 = bm + wr + mi * 16 + g;
            int cn = bn + wc + ni * 8 + 2 * q;
            float v0 = acc[mi][ni][0], v1 = acc[mi][ni][1];
            float v2 = acc[mi][ni][2], v3 = acc[mi][ni][3];
            if (RELU) {
                v0 = fmaxf(v0, 0.0f); v1 = fmaxf(v1, 0.0f);
                v2 = fmaxf(v2, 0.0f); v3 = fmaxf(v3, 0.0f);
            }
            if (ADD) {
                float2 s0 = *(const float2*)(Src + (size_t)r0 * N + cn);
                float2 s1 = *(const float2*)(Src + (size_t)(r0 + 8) * N + cn);
                v0 += s0.x; v1 += s0.y; v2 += s1.x; v3 += s1.y;
            }
            if (TFOUT) {
                v0 = tf32r(v0); v1 = tf32r(v1); v2 = tf32r(v2); v3 = tf32r(v3);
            }
            *(float2*)(C + (size_t)r0 * N + cn)       = make_float2(v0, v1);
            *(float2*)(C + (size_t)(r0 + 8) * N + cn) = make_float2(v2, v3);
        }
    }
}

// ---------------- kernel 3: tf32 flash attention + residual ----------------
#define SC 64
__global__ __launch_bounds__(256) void attn_mma_kernel(
        const float* __restrict__ qp, const float* __restrict__ kp,
        const float* __restrict__ vp, const float* __restrict__ qin,
        const int* __restrict__ qlens, const int* __restrict__ klens,
        float* __restrict__ res) {
    __shared__ uint32_t Ks[SC][68];
    __shared__ uint32_t Vs[SC][72];

    int b = blockIdx.z, h = blockIdx.y;
    int t0 = blockIdx.x * 128;
    int tid = threadIdx.x, lane = tid & 31, warp = tid >> 5;
    int g = lane >> 2, q = lane & 3;
    int klen = klens[b];
    int qlen = qlens[b];
    size_t base = ((size_t)b * TT) * DD + h * DHH;
    int rbase = t0 + warp * 16;

    float O[8][4];
    #pragma unroll
    for (int ni = 0; ni < 8; ni++)
        #pragma unroll
        for (int r = 0; r < 4; r++) O[ni][r] = 0.0f;
    float l0 = 0.0f, l1 = 0.0f;

    if (t0 < qlen) {
        uint32_t aQ[8][4];
        {
            const float* q0 = qp + base + (size_t)(rbase + g) * DD;
            const float* q8 = qp + base + (size_t)(rbase + g + 8) * DD;
            #pragma unroll
            for (int kk = 0; kk < 8; kk++) {
                int c = kk * 8 + q;
                aQ[kk][0] = f2tf32(q0[c] * 0.125f);
                aQ[kk][1] = f2tf32(q8[c] * 0.125f);
                aQ[kk][2] = f2tf32(q0[c + 4] * 0.125f);
                aQ[kk][3] = f2tf32(q8[c + 4] * 0.125f);
            }
        }

        float m0 = -1e30f, m1 = -1e30f;
        int nchunks = (klen + SC - 1) / SC;

        for (int ch = 0; ch < nchunks; ch++) {
            int s0 = ch * SC;
            __syncthreads();
            #pragma unroll
            for (int i = 0; i < 4; i++) {
                int c = tid + i * 256;
                int row = c >> 4;
                int col = (c & 15) * 4;
                size_t off = base + (size_t)(s0 + row) * DD + col;
                float4 kv4 = *(const float4*)(kp + off);
                Ks[row][col + 0] = __float_as_uint(kv4.x);
                Ks[row][col + 1] = __float_as_uint(kv4.y);
                Ks[row][col + 2] = __float_as_uint(kv4.z);
                Ks[row][col + 3] = __float_as_uint(kv4.w);
                float4 vv4 = *(const float4*)(vp + off);
                Vs[row][col + 0] = __float_as_uint(vv4.x);
                Vs[row][col + 1] = __float_as_uint(vv4.y);
                Vs[row][col + 2] = __float_as_uint(vv4.z);
                Vs[row][col + 3] = __float_as_uint(vv4.w);
            }
            __syncthreads();

            float sacc[8][4];
            #pragma unroll
            for (int ni = 0; ni < 8; ni++)
                #pragma unroll
                for (int r = 0; r < 4; r++) sacc[ni][r] = 0.0f;
            #pragma unroll
            for (int kk = 0; kk < 8; kk++) {
                #pragma unroll
                for (int ni = 0; ni < 8; ni++) {
                    uint32_t b0 = Ks[ni * 8 + g][kk * 8 + q];
                    uint32_t b1 = Ks[ni * 8 + g][kk * 8 + q + 4];
                    asm volatile(
                        "mma.sync.aligned.m16n8k8.row.col.f32.tf32.tf32.f32 "
                        "{%0,%1,%2,%3},{%4,%5,%6,%7},{%8,%9},{%0,%1,%2,%3};"
                        : "+f"(sacc[ni][0]), "+f"(sacc[ni][1]),
                          "+f"(sacc[ni][2]), "+f"(sacc[ni][3])
                        : "r"(aQ[kk][0]), "r"(aQ[kk][1]), "r"(aQ[kk][2]), "r"(aQ[kk][3]),
                          "r"(b0), "r"(b1));
                }
            }

            int cb = s0 + 2 * q;
            #pragma unroll
            for (int ni = 0; ni < 8; ni++) {
                if (cb + ni * 8     >= klen) { sacc[ni][0] = -1e30f; sacc[ni][2] = -1e30f; }
                if (cb + ni * 8 + 1 >= klen) { sacc[ni][1] = -1e30f; sacc[ni][3] = -1e30f; }
            }

            float mc0 = -1e30f, mc1 = -1e30f;
            #pragma unroll
            for (int ni = 0; ni < 8; ni++) {
                mc0 = fmaxf(mc0, fmaxf(sacc[ni][0], sacc[ni][1]));
                mc1 = fmaxf(mc1, fmaxf(sacc[ni][2], sacc[ni][3]));
            }
            #pragma unroll
            for (int o = 1; o <= 2; o <<= 1) {
                mc0 = fmaxf(mc0, __shfl_xor_sync(0xffffffffu, mc0, o));
                mc1 = fmaxf(mc1, __shfl_xor_sync(0xffffffffu, mc1, o));
            }
            float mn0 = fmaxf(m0, mc0), mn1 = fmaxf(m1, mc1);
            float al0 = __expf(m0 - mn0), al1 = __expf(m1 - mn1);
            m0 = mn0; m1 = mn1;

            float rs0 = 0.0f, rs1 = 0.0f;
            #pragma unroll
            for (int ni = 0; ni < 8; ni++) {
                float p0 = __expf(sacc[ni][0] - m0);
                float p1 = __expf(sacc[ni][1] - m0);
                float p2 = __expf(sacc[ni][2] - m1);
                float p3 = __expf(sacc[ni][3] - m1);
                rs0 += p0 + p1; rs1 += p2 + p3;
                sacc[ni][0] = p0; sacc[ni][1] = p1; sacc[ni][2] = p2; sacc[ni][3] = p3;
            }
            #pragma unroll
            for (int o = 1; o <= 2; o <<= 1) {
                rs0 += __shfl_xor_sync(0xffffffffu, rs0, o);
                rs1 += __shfl_xor_sync(0xffffffffu, rs1, o);
            }
            l0 = l0 * al0 + rs0;
            l1 = l1 * al1 + rs1;
            #pragma unroll
            for (int ni = 0; ni < 8; ni++) {
                O[ni][0] *= al0; O[ni][1] *= al0;
                O[ni][2] *= al1; O[ni][3] *= al1;
            }

            int srcA = g * 4 + (q >> 1);
            int srcB = srcA + 2;
            bool odd = (q & 1);
            #pragma unroll
            for (int ks = 0; ks < 8; ks++) {
                float v00 = __shfl_sync(0xffffffffu, sacc[ks][0], srcA);
                float v01 = __shfl_sync(0xffffffffu, sacc[ks][1], srcA);
                float v10 = __shfl_sync(0xffffffffu, sacc[ks][2], srcA);
                float v11 = __shfl_sync(0xffffffffu, sacc[ks][3], srcA);
                float w00 = __shfl_sync(0xffffffffu, sacc[ks][0], srcB);
                float w01 = __shfl_sync(0xffffffffu, sacc[ks][1], srcB);
                float w10 = __shfl_sync(0xffffffffu, sacc[ks][2], srcB);
                float w11 = __shfl_sync(0xffffffffu, sacc[ks][3], srcB);
                uint32_t a0 = f2tf32(odd ? v01 : v00);
                uint32_t a1 = f2tf32(odd ? v11 : v10);
                uint32_t a2 = f2tf32(odd ? w01 : w00);
                uint32_t a3 = f2tf32(odd ? w11 : w10);
                #pragma unroll
                for (int ni = 0; ni < 8; ni++) {
                    uint32_t b0 = Vs[ks * 8 + q    ][ni * 8 + g];
                    uint32_t b1 = Vs[ks * 8 + q + 4][ni * 8 + g];
                    asm volatile(
                        "mma.sync.aligned.m16n8k8.row.col.f32.tf32.tf32.f32 "
                        "{%0,%1,%2,%3},{%4,%5,%6,%7},{%8,%9},{%0,%1,%2,%3};"
                        : "+f"(O[ni][0]), "+f"(O[ni][1]),
                          "+f"(O[ni][2]), "+f"(O[ni][3])
                        : "r"(a0), "r"(a1), "r"(a2), "r"(a3),
                          "r"(b0), "r"(b1));
                }
            }
        }
    }

    float inv0 = (l0 > 0.0f) ? 1.0f / l0 : 0.0f;
    float inv1 = (l1 > 0.0f) ? 1.0f / l1 : 0.0f;
    int r0 = rbase + g, r1 = rbase + g + 8;
    float s0f = (r0 < qlen) ? inv0 : 0.0f;
    float s1f = (r1 < qlen) ? inv1 : 0.0f;
    size_t off0 = base + (size_t)r0 * DD + 2 * q;
    size_t off1 = base + (size_t)r1 * DD + 2 * q;
    #pragma unroll
    for (int ni = 0; ni < 8; ni++) {
        float2 i0 = *(const float2*)(qin + off0 + ni * 8);
        float2 i1 = *(const float2*)(qin + off1 + ni * 8);
        float2 o0 = make_float2(tf32r(i0.x + O[ni][0] * s0f), tf32r(i0.y + O[ni][1] * s0f));
        float2 o1 = make_float2(tf32r(i1.x + O[ni][2] * s1f), tf32r(i1.y + O[ni][3] * s1f));
        *(float2*)(res + off0 + ni * 8) = o0;
        *(float2*)(res + off1 + ni * 8) = o1;
    }
}

// ---------------- kernel 4: mean over T ----------------
__global__ void mean_kernel(const float* __restrict__ x, float* __restrict__ out) {
    int d = blockIdx.x * blockDim.x + threadIdx.x;
    int b = blockIdx.y;
    if (d >= DD) return;
    float s = 0.0f;
    const float* p = x + ((size_t)b * TT) * DD + d;
    for (int t = 0; t < TT; t++) s += p[(size_t)t * DD];
    out[b * DD + d] = s * (1.0f / (float)TT);
}

// ---------------- launch ----------------
extern "C" void kernel_launch(void* const* d_in, const int* in_sizes, int n_in,
                              void* d_out, int out_size) {
    const float* queries = (const float*)d_in[0];
    const float* keys    = (const float*)d_in[1];
    const int*   qlens   = (const int*)d_in[2];
    const int*   klens   = (const int*)d_in[3];
    const float* W_Q     = (const float*)d_in[4];
    const float* W_K     = (const float*)d_in[5];
    const float* W_V     = (const float*)d_in[6];
    const float* fw1     = (const float*)d_in[7];
    const float* fw2     = (const float*)d_in[8];
    float* out = (float*)d_out;

    float *qin, *kin, *qp, *kp, *vp, *resb, *hid, *res2;
    float *wq, *wk, *wv, *f1, *f2;
    cudaGetSymbolAddress((void**)&qin,  g_qin);
    cudaGetSymbolAddress((void**)&kin,  g_kin);
    cudaGetSymbolAddress((void**)&qp,   g_qp);
    cudaGetSymbolAddress((void**)&kp,   g_kp);
    cudaGetSymbolAddress((void**)&vp,   g_vp);
    cudaGetSymbolAddress((void**)&resb, g_res);
    cudaGetSymbolAddress((void**)&hid,  g_hid);
    cudaGetSymbolAddress((void**)&res2, g_res2);
    cudaGetSymbolAddress((void**)&wq,   g_wq);
    cudaGetSymbolAddress((void**)&wk,   g_wk);
    cudaGetSymbolAddress((void**)&wv,   g_wv);
    cudaGetSymbolAddress((void**)&f1,   g_f1);
    cudaGetSymbolAddress((void**)&f2,   g_f2);

    const int M = BB * TT;          // 32768
    const int n_elem = BB * TT * DD;
    const int GEMM_SMEM = 3 * (128 * 36 + 32 * 136) * 4;  // 107520 B

    cudaFuncSetAttribute(tf32_gemm_v8<false, false, true>,
                         cudaFuncAttributeMaxDynamicSharedMemorySize, GEMM_SMEM);
    cudaFuncSetAttribute(tf32_gemm_v8<true, false, true>,
                         cudaFuncAttributeMaxDynamicSharedMemorySize, GEMM_SMEM);
    cudaFuncSetAttribute(tf32_gemm_v8<false, true, false>,
                         cudaFuncAttributeMaxDynamicSharedMemorySize, GEMM_SMEM);

    // 0. round weights to tf32 (one launch)
    roundw_all_kernel<<<(DD * 4 * DD + 255) / 256, 256>>>(
        W_Q, wq, W_K, wk, W_V, wv, fw1, f1, fw2, f2);

    addpe_kernel<<<(n_elem + 255) / 256, 256>>>(queries, keys, qin, kin);

    dim3 gproj(DD / 128, M / 128);
    tf32_gemm_v8<false, false, true><<<gproj, 256, GEMM_SMEM>>>(qin, wq, nullptr, qp, M, DD, DD);
    tf32_gemm_v8<false, false, true><<<gproj, 256, GEMM_SMEM>>>(kin, wk, nullptr, kp, M, DD, DD);
    tf32_gemm_v8<false, false, true><<<gproj, 256, GEMM_SMEM>>>(kp, wv, nullptr, vp, M, DD, DD);

    dim3 gattn(TT / 128, HH, BB);
    attn_mma_kernel<<<gattn, 256>>>(qp, kp, vp, qin, qlens, klens, resb);

    dim3 gff1((4 * DD) / 128, M / 128);
    tf32_gemm_v8<true, false, true><<<gff1, 256, GEMM_SMEM>>>(resb, f1, nullptr, hid, M, 4 * DD, DD);

    dim3 gff2(DD / 128, M / 128);
    tf32_gemm_v8<false, true, false><<<gff2, 256, GEMM_SMEM>>>(hid, f2, resb, res2, M, DD, 4 * DD);

    dim3 gmean(DD / 128, BB);
    mean_kernel<<<gmean, 128>>>(res2, out);
}

// round 16
// speedup vs baseline: 1.0034x; 1.0034x over previous
#include <cuda_runtime.h>
#include <cuda_bf16.h>
#include <math.h>
#include <stdint.h>

// Problem constants
#define BB 64
#define TT 512
#define DD 512
#define HH 8
#define DHH 64

// ---------------- scratch (device globals; allocation-free) ----------------
__device__ float g_qin[BB * TT * DD];
__device__ float g_kin[BB * TT * DD];
__device__ float g_qp [BB * TT * DD];
__device__ float g_kp [BB * TT * DD];
__device__ float g_vp [BB * TT * DD];
__device__ float g_res[BB * TT * DD];
__device__ float g_hid[BB * TT * 4 * DD];
__device__ float g_res2[BB * TT * DD];
// tf32-rounded weight copies (+ fused K*V weight)
__device__ float g_wq[DD * DD];
__device__ float g_wk[DD * DD];
__device__ float g_wv[DD * DD];
__device__ float g_wkv[DD * DD];
__device__ float g_f1[DD * 4 * DD];
__device__ float g_f2[4 * DD * DD];

__device__ __forceinline__ uint32_t f2tf32(float x) {
    uint32_t r;
    asm("cvt.rna.tf32.f32 %0, %1;" : "=r"(r) : "f"(x));
    return r;
}
__device__ __forceinline__ float tf32r(float x) {
    return __uint_as_float(f2tf32(x));
}

#define CPASYNC16(dst, src) \
    asm volatile("cp.async.cg.shared.global [%0], [%1], 16;" :: "r"(dst), "l"(src))

// ---------------- kernel 0: round all weights to tf32 (single launch) ----------------
__global__ void roundw_all_kernel(const float* __restrict__ wq0, float* __restrict__ wq1,
                                  const float* __restrict__ wk0, float* __restrict__ wk1,
                                  const float* __restrict__ wv0, float* __restrict__ wv1,
                                  const float* __restrict__ f10, float* __restrict__ f11,
                                  const float* __restrict__ f20, float* __restrict__ f21) {
    int i = blockIdx.x * blockDim.x + threadIdx.x;
    if (i < DD * DD) {
        wq1[i] = tf32r(wq0[i]);
        wk1[i] = tf32r(wk0[i]);
        wv1[i] = tf32r(wv0[i]);
    }
    if (i < DD * 4 * DD) {
        f11[i] = tf32r(f10[i]);
        f21[i] = tf32r(f20[i]);
    }
}

// ---------------- kernel 1: positional encoding add (tf32-rounded out) ----------------
__global__ void addpe_kernel(const float* __restrict__ q, const float* __restrict__ k,
                             float* __restrict__ qo, float* __restrict__ ko) {
    int idx = blockIdx.x * blockDim.x + threadIdx.x;
    if (idx >= BB * TT * DD) return;
    int d = idx % DD;
    int t = (idx / DD) % TT;
    int j = (d < DD / 2) ? d : d - DD / 2;
    float invf = expf(-(2.0f * (float)j / (float)DD) * 9.210340371976184f); // ln(10000)
    float arg = (float)t * invf;
    float pe = (d < DD / 2) ? cosf(arg) : sinf(arg);
    qo[idx] = tf32r(q[idx] + pe);
    ko[idx] = tf32r(k[idx] + pe);
}

// ---------------- TF32 GEMM body (v5 design): 128x128 tile, 64x32 warp tile ----------------
// 3-stage cp.async, 1 barrier/K-tile, ldmatrix A, conflict-free B (stride 136).
template<bool RELU, bool ADD, bool TFOUT>
__device__ __forceinline__ void gemm_body(
        const float* __restrict__ A, const float* __restrict__ W,
        const float* __restrict__ Src, float* __restrict__ C,
        int M, int N, int K, uint32_t* sm) {
    const int BK = 32;
    const int AST = 36, BST = 136;
    const int ASTAGE = 128 * AST, BSTAGE = 32 * BST;
    const int STAGE = ASTAGE + BSTAGE;        // 8960 u32 per stage

    int tid = threadIdx.x;
    int lane = tid & 31, warp = tid >> 5;
    int wr = (warp >> 2) * 64;
    int wc = (warp & 3) * 32;
    int bm = blockIdx.y * 128, bn = blockIdx.x * 128;
    int g = lane >> 2, q = lane & 3;

    uint32_t smem_base = (uint32_t)__cvta_generic_to_shared(sm);

    int lrow = ((lane >> 3) & 1) * 8 + (lane & 7);
    int lcol = (lane >> 4) * 4;

    float acc[4][4][4];
    #pragma unroll
    for (int mi = 0; mi < 4; mi++)
        #pragma unroll
        for (int ni = 0; ni < 4; ni++)
            #pragma unroll
            for (int r = 0; r < 4; r++) acc[mi][ni][r] = 0.0f;

    auto stage_load = [&](int k0, int s) {
        uint32_t abase = smem_base + (uint32_t)(s * STAGE) * 4u;
        uint32_t bbase = abase + (uint32_t)ASTAGE * 4u;
        #pragma unroll
        for (int i = 0; i < 4; i++) {
            int c = tid + i * 256;
            int row = c >> 3, col = (c & 7) * 4;
            CPASYNC16(abase + (uint32_t)(row * AST + col) * 4u,
                      A + (size_t)(bm + row) * K + k0 + col);
        }
        #pragma unroll
        for (int i = 0; i < 4; i++) {
            int c = tid + i * 256;
            int kr = c >> 5, col = (c & 31) * 4;
            CPASYNC16(bbase + (uint32_t)(kr * BST + col) * 4u,
                      W + (size_t)(k0 + kr) * N + bn + col);
        }
        asm volatile("cp.async.commit_group;");
    };

    int nk = K / BK;
    stage_load(0, 0);
    stage_load(BK, 1);

    for (int it = 0; it < nk; it++) {
        asm volatile("cp.async.wait_group 1;");
        __syncthreads();
        if (it + 2 < nk) stage_load((it + 2) * BK, (it + 2) % 3);
        else asm volatile("cp.async.commit_group;");

        int s = it % 3;
        uint32_t abuf = smem_base + (uint32_t)(s * STAGE) * 4u;
        const uint32_t* Bb = sm + s * STAGE + ASTAGE;
        #pragma unroll
        for (int kk = 0; kk < BK; kk += 8) {
            uint32_t af[4][4];
            #pragma unroll
            for (int mi = 0; mi < 4; mi++) {
                uint32_t addr = abuf +
                    (uint32_t)((wr + mi * 16 + lrow) * AST + kk + lcol) * 4u;
                asm volatile(
                    "ldmatrix.sync.aligned.m8n8.x4.shared.b16 {%0,%1,%2,%3}, [%4];"
                    : "=r"(af[mi][0]), "=r"(af[mi][1]),
                      "=r"(af[mi][2]), "=r"(af[mi][3])
                    : "r"(addr));
            }
            uint32_t bf[4][2];
            #pragma unroll
            for (int ni = 0; ni < 4; ni++) {
                int cn = wc + ni * 8 + g;
                bf[ni][0] = Bb[(kk + q) * BST + cn];
                bf[ni][1] = Bb[(kk + 4 + q) * BST + cn];
            }
            #pragma unroll
            for (int mi = 0; mi < 4; mi++)
                #pragma unroll
                for (int ni = 0; ni < 4; ni++) {
                    asm volatile(
                        "mma.sync.aligned.m16n8k8.row.col.f32.tf32.tf32.f32 "
                        "{%0,%1,%2,%3},{%4,%5,%6,%7},{%8,%9},{%0,%1,%2,%3};"
                        : "+f"(acc[mi][ni][0]), "+f"(acc[mi][ni][1]),
                          "+f"(acc[mi][ni][2]), "+f"(acc[mi][ni][3])
                        : "r"(af[mi][0]), "r"(af[mi][1]), "r"(af[mi][2]), "r"(af[mi][3]),
                          "r"(bf[ni][0]), "r"(bf[ni][1]));
                }
        }
    }

    #pragma unroll
    for (int mi = 0; mi < 4; mi++) {
        #pragma unroll
        for (int ni = 0; ni < 4; ni++) {
            int r0 = bm + wr + mi * 16 + g;
            int cn = bn + wc + ni * 8 + 2 * q;
            float v0 = acc[mi][ni][0], v1 = acc[mi][ni][1];
            float v2 = acc[mi][ni][2], v3 = acc[mi][ni][3];
            if (RELU) {
                v0 = fmaxf(v0, 0.0f); v1 = fmaxf(v1, 0.0f);
                v2 = fmaxf(v2, 0.0f); v3 = fmaxf(v3, 0.0f);
            }
            if (ADD) {
                float2 s0 = *(const float2*)(Src + (size_t)r0 * N + cn);
                float2 s1 = *(const float2*)(Src + (size_t)(r0 + 8) * N + cn);
                v0 += s0.x; v1 += s0.y; v2 += s1.x; v3 += s1.y;
            }
            if (TFOUT) {
                v0 = tf32r(v0); v1 = tf32r(v1); v2 = tf32r(v2); v3 = tf32r(v3);
            }
            *(float2*)(C + (size_t)r0 * N + cn)       = make_float2(v0, v1);
            *(float2*)(C + (size_t)(r0 + 8) * N + cn) = make_float2(v2, v3);
        }
    }
}

// generic single-GEMM kernel
template<bool RELU, bool ADD, bool TFOUT>
__global__ __launch_bounds__(256, 2) void tf32_gemm_k(
        const float* __restrict__ A, const float* __restrict__ W,
        const float* __restrict__ Src, float* __restrict__ C,
        int M, int N, int K) {
    extern __shared__ uint32_t sm[];
    gemm_body<RELU, ADD, TFOUT>(A, W, Src, C, M, N, K, sm);
}

// batched projection kernel: blockIdx.z selects (A, W, C); all M x 512 x 512
__global__ __launch_bounds__(256, 2) void proj3_kernel(
        const float* __restrict__ qin, const float* __restrict__ kin,
        const float* __restrict__ wq, const float* __restrict__ wk,
        const float* __restrict__ wkv,
        float* __restrict__ qp, float* __restrict__ kp, float* __restrict__ vp,
        int M) {
    extern __shared__ uint32_t sm[];
    const float* A;
    const float* W;
    float* C;
    if (blockIdx.z == 0)      { A = qin; W = wq;  C = qp; }
    else if (blockIdx.z == 1) { A = kin; W = wk;  C = kp; }
    else                      { A = kin; W = wkv; C = vp; }
    gemm_body<false, false, true>(A, W, nullptr, C, M, DD, DD, sm);
}

// ---------------- kernel 3: tf32 flash attention + residual ----------------
#define SC 64
__global__ __launch_bounds__(256) void attn_mma_kernel(
        const float* __restrict__ qp, const float* __restrict__ kp,
        const float* __restrict__ vp, const float* __restrict__ qin,
        const int* __restrict__ qlens, const int* __restrict__ klens,
        float* __restrict__ res) {
    __shared__ uint32_t Ks[SC][68];
    __shared__ uint32_t Vs[SC][72];

    int b = blockIdx.z, h = blockIdx.y;
    int t0 = blockIdx.x * 128;
    int tid = threadIdx.x, lane = tid & 31, warp = tid >> 5;
    int g = lane >> 2, q = lane & 3;
    int klen = klens[b];
    int qlen = qlens[b];
    size_t base = ((size_t)b * TT) * DD + h * DHH;
    int rbase = t0 + warp * 16;

    float O[8][4];
    #pragma unroll
    for (int ni = 0; ni < 8; ni++)
        #pragma unroll
        for (int r = 0; r < 4; r++) O[ni][r] = 0.0f;
    float l0 = 0.0f, l1 = 0.0f;

    if (t0 < qlen) {
        uint32_t aQ[8][4];
        {
            const float* q0 = qp + base + (size_t)(rbase + g) * DD;
            const float* q8 = qp + base + (size_t)(rbase + g + 8) * DD;
            #pragma unroll
            for (int kk = 0; kk < 8; kk++) {
                int c = kk * 8 + q;
                aQ[kk][0] = f2tf32(q0[c] * 0.125f);
                aQ[kk][1] = f2tf32(q8[c] * 0.125f);
                aQ[kk][2] = f2tf32(q0[c + 4] * 0.125f);
                aQ[kk][3] = f2tf32(q8[c + 4] * 0.125f);
            }
        }

        float m0 = -1e30f, m1 = -1e30f;
        int nchunks = (klen + SC - 1) / SC;

        for (int ch = 0; ch < nchunks; ch++) {
            int s0 = ch * SC;
            __syncthreads();
            #pragma unroll
            for (int i = 0; i < 4; i++) {
                int c = tid + i * 256;
                int row = c >> 4;
                int col = (c & 15) * 4;
                size_t off = base + (size_t)(s0 + row) * DD + col;
                float4 kv4 = *(const float4*)(kp + off);
                Ks[row][col + 0] = __float_as_uint(kv4.x);
                Ks[row][col + 1] = __float_as_uint(kv4.y);
                Ks[row][col + 2] = __float_as_uint(kv4.z);
                Ks[row][col + 3] = __float_as_uint(kv4.w);
                float4 vv4 = *(const float4*)(vp + off);
                Vs[row][col + 0] = __float_as_uint(vv4.x);
                Vs[row][col + 1] = __float_as_uint(vv4.y);
                Vs[row][col + 2] = __float_as_uint(vv4.z);
                Vs[row][col + 3] = __float_as_uint(vv4.w);
            }
            __syncthreads();

            float sacc[8][4];
            #pragma unroll
            for (int ni = 0; ni < 8; ni++)
                #pragma unroll
                for (int r = 0; r < 4; r++) sacc[ni][r] = 0.0f;
            #pragma unroll
            for (int kk = 0; kk < 8; kk++) {
                #pragma unroll
                for (int ni = 0; ni < 8; ni++) {
                    uint32_t b0 = Ks[ni * 8 + g][kk * 8 + q];
                    uint32_t b1 = Ks[ni * 8 + g][kk * 8 + q + 4];
                    asm volatile(
                        "mma.sync.aligned.m16n8k8.row.col.f32.tf32.tf32.f32 "
                        "{%0,%1,%2,%3},{%4,%5,%6,%7},{%8,%9},{%0,%1,%2,%3};"
                        : "+f"(sacc[ni][0]), "+f"(sacc[ni][1]),
                          "+f"(sacc[ni][2]), "+f"(sacc[ni][3])
                        : "r"(aQ[kk][0]), "r"(aQ[kk][1]), "r"(aQ[kk][2]), "r"(aQ[kk][3]),
                          "r"(b0), "r"(b1));
                }
            }

            int cb = s0 + 2 * q;
            #pragma unroll
            for (int ni = 0; ni < 8; ni++) {
                if (cb + ni * 8     >= klen) { sacc[ni][0] = -1e30f; sacc[ni][2] = -1e30f; }
                if (cb + ni * 8 + 1 >= klen) { sacc[ni][1] = -1e30f; sacc[ni][3] = -1e30f; }
            }

            float mc0 = -1e30f, mc1 = -1e30f;
            #pragma unroll
            for (int ni = 0; ni < 8; ni++) {
                mc0 = fmaxf(mc0, fmaxf(sacc[ni][0], sacc[ni][1]));
                mc1 = fmaxf(mc1, fmaxf(sacc[ni][2], sacc[ni][3]));
            }
            #pragma unroll
            for (int o = 1; o <= 2; o <<= 1) {
                mc0 = fmaxf(mc0, __shfl_xor_sync(0xffffffffu, mc0, o));
                mc1 = fmaxf(mc1, __shfl_xor_sync(0xffffffffu, mc1, o));
            }
            float mn0 = fmaxf(m0, mc0), mn1 = fmaxf(m1, mc1);
            float al0 = __expf(m0 - mn0), al1 = __expf(m1 - mn1);
            m0 = mn0; m1 = mn1;

            float rs0 = 0.0f, rs1 = 0.0f;
            #pragma unroll
            for (int ni = 0; ni < 8; ni++) {
                float p0 = __expf(sacc[ni][0] - m0);
                float p1 = __expf(sacc[ni][1] - m0);
                float p2 = __expf(sacc[ni][2] - m1);
                float p3 = __expf(sacc[ni][3] - m1);
                rs0 += p0 + p1; rs1 += p2 + p3;
                sacc[ni][0] = p0; sacc[ni][1] = p1; sacc[ni][2] = p2; sacc[ni][3] = p3;
            }
            #pragma unroll
            for (int o = 1; o <= 2; o <<= 1) {
                rs0 += __shfl_xor_sync(0xffffffffu, rs0, o);
                rs1 += __shfl_xor_sync(0xffffffffu, rs1, o);
            }
            l0 = l0 * al0 + rs0;
            l1 = l1 * al1 + rs1;
            #pragma unroll
            for (int ni = 0; ni < 8; ni++) {
                O[ni][0] *= al0; O[ni][1] *= al0;
                O[ni][2] *= al1; O[ni][3] *= al1;
            }

            int srcA = g * 4 + (q >> 1);
            int srcB = srcA + 2;
            bool odd = (q & 1);
            #pragma unroll
            for (int ks = 0; ks < 8; ks++) {
                float v00 = __shfl_sync(0xffffffffu, sacc[ks][0], srcA);
                float v01 = __shfl_sync(0xffffffffu, sacc[ks][1], srcA);
                float v10 = __shfl_sync(0xffffffffu, sacc[ks][2], srcA);
                float v11 = __shfl_sync(0xffffffffu, sacc[ks][3], srcA);
                float w00 = __shfl_sync(0xffffffffu, sacc[ks][0], srcB);
                float w01 = __shfl_sync(0xffffffffu, sacc[ks][1], srcB);
                float w10 = __shfl_sync(0xffffffffu, sacc[ks][2], srcB);
                float w11 = __shfl_sync(0xffffffffu, sacc[ks][3], srcB);
                uint32_t a0 = f2tf32(odd ? v01 : v00);
                uint32_t a1 = f2tf32(odd ? v11 : v10);
                uint32_t a2 = f2tf32(odd ? w01 : w00);
                uint32_t a3 = f2tf32(odd ? w11 : w10);
                #pragma unroll
                for (int ni = 0; ni < 8; ni++) {
                    uint32_t b0 = Vs[ks * 8 + q    ][ni * 8 + g];
                    uint32_t b1 = Vs[ks * 8 + q + 4][ni * 8 + g];
                    asm volatile(
                        "mma.sync.aligned.m16n8k8.row.col.f32.tf32.tf32.f32 "
                        "{%0,%1,%2,%3},{%4,%5,%6,%7},{%8,%9},{%0,%1,%2,%3};"
                        : "+f"(O[ni][0]), "+f"(O[ni][1]),
                          "+f"(O[ni][2]), "+f"(O[ni][3])
                        : "r"(a0), "r"(a1), "r"(a2), "r"(a3),
                          "r"(b0), "r"(b1));
                }
            }
        }
    }

    float inv0 = (l0 > 0.0f) ? 1.0f / l0 : 0.0f;
    float inv1 = (l1 > 0.0f) ? 1.0f / l1 : 0.0f;
    int r0 = rbase + g, r1 = rbase + g + 8;
    float s0f = (r0 < qlen) ? inv0 : 0.0f;
    float s1f = (r1 < qlen) ? inv1 : 0.0f;
    size_t off0 = base + (size_t)r0 * DD + 2 * q;
    size_t off1 = base + (size_t)r1 * DD + 2 * q;
    #pragma unroll
    for (int ni = 0; ni < 8; ni++) {
        float2 i0 = *(const float2*)(qin + off0 + ni * 8);
        float2 i1 = *(const float2*)(qin + off1 + ni * 8);
        float2 o0 = make_float2(tf32r(i0.x + O[ni][0] * s0f), tf32r(i0.y + O[ni][1] * s0f));
        float2 o1 = make_float2(tf32r(i1.x + O[ni][2] * s1f), tf32r(i1.y + O[ni][3] * s1f));
        *(float2*)(res + off0 + ni * 8) = o0;
        *(float2*)(res + off1 + ni * 8) = o1;
    }
}

// ---------------- kernel 4: mean over T ----------------
__global__ void mean_kernel(const float* __restrict__ x, float* __restrict__ out) {
    int d = blockIdx.x * blockDim.x + threadIdx.x;
    int b = blockIdx.y;
    if (d >= DD) return;
    float s = 0.0f;
    const float* p = x + ((size_t)b * TT) * DD + d;
    for (int t = 0; t < TT; t++) s += p[(size_t)t * DD];
    out[b * DD + d] = s * (1.0f / (float)TT);
}

// ---------------- launch ----------------
extern "C" void kernel_launch(void* const* d_in, const int* in_sizes, int n_in,
                              void* d_out, int out_size) {
    const float* queries = (const float*)d_in[0];
    const float* keys    = (const float*)d_in[1];
    const int*   qlens   = (const int*)d_in[2];
    const int*   klens   = (const int*)d_in[3];
    const float* W_Q     = (const float*)d_in[4];
    const float* W_K     = (const float*)d_in[5];
    const float* W_V     = (const float*)d_in[6];
    const float* fw1     = (const float*)d_in[7];
    const float* fw2     = (const float*)d_in[8];
    float* out = (float*)d_out;

    float *qin, *kin, *qp, *kp, *vp, *resb, *hid, *res2;
    float *wq, *wk, *wv, *wkv, *f1, *f2;
    cudaGetSymbolAddress((void**)&qin,  g_qin);
    cudaGetSymbolAddress((void**)&kin,  g_kin);
    cudaGetSymbolAddress((void**)&qp,   g_qp);
    cudaGetSymbolAddress((void**)&kp,   g_kp);
    cudaGetSymbolAddress((void**)&vp,   g_vp);
    cudaGetSymbolAddress((void**)&resb, g_res);
    cudaGetSymbolAddress((void**)&hid,  g_hid);
    cudaGetSymbolAddress((void**)&res2, g_res2);
    cudaGetSymbolAddress((void**)&wq,   g_wq);
    cudaGetSymbolAddress((void**)&wk,   g_wk);
    cudaGetSymbolAddress((void**)&wv,   g_wv);
    cudaGetSymbolAddress((void**)&wkv,  g_wkv);
    cudaGetSymbolAddress((void**)&f1,   g_f1);
    cudaGetSymbolAddress((void**)&f2,   g_f2);

    const int M = BB * TT;          // 32768
    const int n_elem = BB * TT * DD;
    const int GEMM_SMEM = 3 * (128 * 36 + 32 * 136) * 4;  // 107520 B

    cudaFuncSetAttribute(tf32_gemm_k<false, false, true>,
                         cudaFuncAttributeMaxDynamicSharedMemorySize, GEMM_SMEM);
    cudaFuncSetAttribute(tf32_gemm_k<true, false, true>,
                         cudaFuncAttributeMaxDynamicSharedMemorySize, GEMM_SMEM);
    cudaFuncSetAttribute(tf32_gemm_k<false, true, false>,
                         cudaFuncAttributeMaxDynamicSharedMemorySize, GEMM_SMEM);
    cudaFuncSetAttribute(proj3_kernel,
                         cudaFuncAttributeMaxDynamicSharedMemorySize, GEMM_SMEM);

    // 0. round weights to tf32
    roundw_all_kernel<<<(DD * 4 * DD + 255) / 256, 256>>>(
        W_Q, wq, W_K, wk, W_V, wv, fw1, f1, fw2, f2);

    // 0b. fuse Wkv = Wk @ Wv (512x512x512, tf32-rounded output)
    tf32_gemm_k<false, false, true><<<dim3(DD / 128, DD / 128), 256, GEMM_SMEM>>>(
        wk, wv, nullptr, wkv, DD, DD, DD);

    // 1. positional encoding
    addpe_kernel<<<(n_elem + 255) / 256, 256>>>(queries, keys, qin, kin);

    // 2. all three projections in one batched launch (independent via Wkv)
    dim3 gproj(DD / 128, M / 128, 3);
    proj3_kernel<<<gproj, 256, GEMM_SMEM>>>(qin, kin, wq, wk, wkv, qp, kp, vp, M);

    // 3. attention + residual
    dim3 gattn(TT / 128, HH, BB);
    attn_mma_kernel<<<gattn, 256>>>(qp, kp, vp, qin, qlens, klens, resb);

    // 4. FFN1
    dim3 gff1((4 * DD) / 128, M / 128);
    tf32_gemm_k<true, false, true><<<gff1, 256, GEMM_SMEM>>>(resb, f1, nullptr, hid, M, 4 * DD, DD);

    // 5. FFN2 + residual
    dim3 gff2(DD / 128, M / 128);
    tf32_gemm_k<false, true, false><<<gff2, 256, GEMM_SMEM>>>(hid, f2, resb, res2, M, DD, 4 * DD);

    // 6. mean
    dim3 gmean(DD / 128, BB);
    mean_kernel<<<gmean, 128>>>(res2, out);
}

// round 17
// speedup vs baseline: 1.3411x; 1.3366x over previous
#include <cuda_runtime.h>
#include <cuda_bf16.h>
#include <math.h>
#include <stdint.h>

// Problem constants
#define BB 64
#define TT 512
#define DD 512
#define HH 8
#define DHH 64
#define FF (4 * DD)              // 2048

// ---------------- scratch (device globals; allocation-free) ----------------
__device__ float g_qin[BB * TT * DD];
__device__ float g_kin[BB * TT * DD];
__device__ float g_qp [BB * TT * DD];
__device__ float g_kp [BB * TT * DD];
__device__ float g_vp [BB * TT * DD];
__device__ float g_res[BB * TT * DD];
__device__ float g_part[(BB * TT / 128) * 2 * FF];   // FFN1 row-partials: [mt][wr2][f]
__device__ float g_meanH[BB * FF];                   // mean over T of relu(res@f1)
// tf32-rounded weight copies (+ fused K*V weight)
__device__ float g_wq[DD * DD];
__device__ float g_wk[DD * DD];
__device__ float g_wv[DD * DD];
__device__ float g_wkv[DD * DD];
__device__ float g_f1[DD * FF];

__device__ __forceinline__ uint32_t f2tf32(float x) {
    uint32_t r;
    asm("cvt.rna.tf32.f32 %0, %1;" : "=r"(r) : "f"(x));
    return r;
}
__device__ __forceinline__ float tf32r(float x) {
    return __uint_as_float(f2tf32(x));
}

#define CPASYNC16(dst, src) \
    asm volatile("cp.async.cg.shared.global [%0], [%1], 16;" :: "r"(dst), "l"(src))

// ---------------- kernel 0: round weights to tf32 (single launch) ----------------
__global__ void roundw_all_kernel(const float* __restrict__ wq0, float* __restrict__ wq1,
                                  const float* __restrict__ wk0, float* __restrict__ wk1,
                                  const float* __restrict__ wv0, float* __restrict__ wv1,
                                  const float* __restrict__ f10, float* __restrict__ f11) {
    int i = blockIdx.x * blockDim.x + threadIdx.x;
    if (i < DD * DD) {
        wq1[i] = tf32r(wq0[i]);
        wk1[i] = tf32r(wk0[i]);
        wv1[i] = tf32r(wv0[i]);
    }
    if (i < DD * FF) {
        f11[i] = tf32r(f10[i]);
    }
}

// ---------------- kernel 1: positional encoding add (tf32-rounded out) ----------------
__global__ void addpe_kernel(const float* __restrict__ q, const float* __restrict__ k,
                             float* __restrict__ qo, float* __restrict__ ko) {
    int idx = blockIdx.x * blockDim.x + threadIdx.x;
    if (idx >= BB * TT * DD) return;
    int d = idx % DD;
    int t = (idx / DD) % TT;
    int j = (d < DD / 2) ? d : d - DD / 2;
    float invf = expf(-(2.0f * (float)j / (float)DD) * 9.210340371976184f); // ln(10000)
    float arg = (float)t * invf;
    float pe = (d < DD / 2) ? cosf(arg) : sinf(arg);
    qo[idx] = tf32r(q[idx] + pe);
    ko[idx] = tf32r(k[idx] + pe);
}

// ---------------- GEMM constants ----------------
#define GBK 32
#define GAST 36
#define GBST 136
#define GASTAGE (128 * GAST)
#define GBSTAGE (32 * GBST)
#define GSTAGE (GASTAGE + GBSTAGE)

// mainloop macro body via device function; returns acc in-place
struct GemmCtx {
    int tid, lane, warp, wr, wc, bm, bn, g, q, lrow, lcol;
    uint32_t smem_base;
    uint32_t* sm;
};

__device__ __forceinline__ void gemm_mainloop(
        const float* __restrict__ A, const float* __restrict__ W,
        int M, int N, int K, GemmCtx& c, float acc[4][4][4]) {
    #pragma unroll
    for (int mi = 0; mi < 4; mi++)
        #pragma unroll
        for (int ni = 0; ni < 4; ni++)
            #pragma unroll
            for (int r = 0; r < 4; r++) acc[mi][ni][r] = 0.0f;

    auto stage_load = [&](int k0, int s) {
        uint32_t abase = c.smem_base + (uint32_t)(s * GSTAGE) * 4u;
        uint32_t bbase = abase + (uint32_t)GASTAGE * 4u;
        #pragma unroll
        for (int i = 0; i < 4; i++) {
            int cc = c.tid + i * 256;
            int row = cc >> 3, col = (cc & 7) * 4;
            CPASYNC16(abase + (uint32_t)(row * GAST + col) * 4u,
                      A + (size_t)(c.bm + row) * K + k0 + col);
        }
        #pragma unroll
        for (int i = 0; i < 4; i++) {
            int cc = c.tid + i * 256;
            int kr = cc >> 5, col = (cc & 31) * 4;
            CPASYNC16(bbase + (uint32_t)(kr * GBST + col) * 4u,
                      W + (size_t)(k0 + kr) * N + c.bn + col);
        }
        asm volatile("cp.async.commit_group;");
    };

    int nk = K / GBK;
    stage_load(0, 0);
    stage_load(GBK, 1);

    for (int it = 0; it < nk; it++) {
        asm volatile("cp.async.wait_group 1;");
        __syncthreads();
        if (it + 2 < nk) stage_load((it + 2) * GBK, (it + 2) % 3);
        else asm volatile("cp.async.commit_group;");

        int s = it % 3;
        uint32_t abuf = c.smem_base + (uint32_t)(s * GSTAGE) * 4u;
        const uint32_t* Bb = c.sm + s * GSTAGE + GASTAGE;
        #pragma unroll
        for (int kk = 0; kk < GBK; kk += 8) {
            uint32_t af[4][4];
            #pragma unroll
            for (int mi = 0; mi < 4; mi++) {
                uint32_t addr = abuf +
                    (uint32_t)((c.wr + mi * 16 + c.lrow) * GAST + kk + c.lcol) * 4u;
                asm volatile(
                    "ldmatrix.sync.aligned.m8n8.x4.shared.b16 {%0,%1,%2,%3}, [%4];"
                    : "=r"(af[mi][0]), "=r"(af[mi][1]),
                      "=r"(af[mi][2]), "=r"(af[mi][3])
                    : "r"(addr));
            }
            uint32_t bf[4][2];
            #pragma unroll
            for (int ni = 0; ni < 4; ni++) {
                int cn = c.wc + ni * 8 + c.g;
                bf[ni][0] = Bb[(kk + c.q) * GBST + cn];
                bf[ni][1] = Bb[(kk + 4 + c.q) * GBST + cn];
            }
            #pragma unroll
            for (int mi = 0; mi < 4; mi++)
                #pragma unroll
                for (int ni = 0; ni < 4; ni++) {
                    asm volatile(
                        "mma.sync.aligned.m16n8k8.row.col.f32.tf32.tf32.f32 "
                        "{%0,%1,%2,%3},{%4,%5,%6,%7},{%8,%9},{%0,%1,%2,%3};"
                        : "+f"(acc[mi][ni][0]), "+f"(acc[mi][ni][1]),
                          "+f"(acc[mi][ni][2]), "+f"(acc[mi][ni][3])
                        : "r"(af[mi][0]), "r"(af[mi][1]), "r"(af[mi][2]), "r"(af[mi][3]),
                          "r"(bf[ni][0]), "r"(bf[ni][1]));
                }
        }
    }
}

__device__ __forceinline__ void gemm_ctx_init(GemmCtx& c, uint32_t* sm) {
    c.tid = threadIdx.x;
    c.lane = c.tid & 31; c.warp = c.tid >> 5;
    c.wr = (c.warp >> 2) * 64;
    c.wc = (c.warp & 3) * 32;
    c.bm = blockIdx.y * 128; c.bn = blockIdx.x * 128;
    c.g = c.lane >> 2; c.q = c.lane & 3;
    c.lrow = ((c.lane >> 3) & 1) * 8 + (c.lane & 7);
    c.lcol = (c.lane >> 4) * 4;
    c.sm = sm;
    c.smem_base = (uint32_t)__cvta_generic_to_shared(sm);
}

// generic single-GEMM kernel (standard store epilogue)
template<bool TFOUT>
__global__ __launch_bounds__(256, 2) void tf32_gemm_k(
        const float* __restrict__ A, const float* __restrict__ W,
        float* __restrict__ C, int M, int N, int K) {
    extern __shared__ uint32_t sm[];
    GemmCtx c; gemm_ctx_init(c, sm);
    float acc[4][4][4];
    gemm_mainloop(A, W, M, N, K, c, acc);
    #pragma unroll
    for (int mi = 0; mi < 4; mi++) {
        #pragma unroll
        for (int ni = 0; ni < 4; ni++) {
            int r0 = c.bm + c.wr + mi * 16 + c.g;
            int cn = c.bn + c.wc + ni * 8 + 2 * c.q;
            float v0 = acc[mi][ni][0], v1 = acc[mi][ni][1];
            float v2 = acc[mi][ni][2], v3 = acc[mi][ni][3];
            if (TFOUT) { v0 = tf32r(v0); v1 = tf32r(v1); v2 = tf32r(v2); v3 = tf32r(v3); }
            *(float2*)(C + (size_t)r0 * N + cn)       = make_float2(v0, v1);
            *(float2*)(C + (size_t)(r0 + 8) * N + cn) = make_float2(v2, v3);
        }
    }
}

// batched projection kernel: blockIdx.z selects (A, W, C)
__global__ __launch_bounds__(256, 2) void proj3_kernel(
        const float* __restrict__ qin, const float* __restrict__ kin,
        const float* __restrict__ wq, const float* __restrict__ wk,
        const float* __restrict__ wkv,
        float* __restrict__ qp, float* __restrict__ kp, float* __restrict__ vp,
        int M) {
    extern __shared__ uint32_t sm[];
    const float* A; const float* W; float* C;
    if (blockIdx.z == 0)      { A = qin; W = wq;  C = qp; }
    else if (blockIdx.z == 1) { A = kin; W = wk;  C = kp; }
    else                      { A = kin; W = wkv; C = vp; }
    GemmCtx c; gemm_ctx_init(c, sm);
    float acc[4][4][4];
    gemm_mainloop(A, W, M, DD, DD, c, acc);
    #pragma unroll
    for (int mi = 0; mi < 4; mi++) {
        #pragma unroll
        for (int ni = 0; ni < 4; ni++) {
            int r0 = c.bm + c.wr + mi * 16 + c.g;
            int cn = c.bn + c.wc + ni * 8 + 2 * c.q;
            *(float2*)(C + (size_t)r0 * DD + cn) =
                make_float2(tf32r(acc[mi][ni][0]), tf32r(acc[mi][ni][1]));
            *(float2*)(C + (size_t)(r0 + 8) * DD + cn) =
                make_float2(tf32r(acc[mi][ni][2]), tf32r(acc[mi][ni][3]));
        }
    }
}

// FFN1 kernel: relu(res @ f1), reduced over the tile's 128 rows -> partials.
// partials[(mt*2 + wr2) * FF + col], mt = blockIdx.y. Deterministic (no atomics).
__global__ __launch_bounds__(256, 2) void ffn1_reduce_kernel(
        const float* __restrict__ A, const float* __restrict__ W,
        float* __restrict__ P, int M) {
    extern __shared__ uint32_t sm[];
    GemmCtx c; gemm_ctx_init(c, sm);
    float acc[4][4][4];
    gemm_mainloop(A, W, M, FF, DD, c, acc);

    // relu + per-thread row-partials per column pair
    float p0[4], p1[4];
    #pragma unroll
    for (int ni = 0; ni < 4; ni++) { p0[ni] = 0.0f; p1[ni] = 0.0f; }
    #pragma unroll
    for (int mi = 0; mi < 4; mi++)
        #pragma unroll
        for (int ni = 0; ni < 4; ni++) {
            p0[ni] += fmaxf(acc[mi][ni][0], 0.0f) + fmaxf(acc[mi][ni][2], 0.0f);
            p1[ni] += fmaxf(acc[mi][ni][1], 0.0f) + fmaxf(acc[mi][ni][3], 0.0f);
        }
    // reduce over g (lanes g*4+q; xor lane bits 2..4)
    #pragma unroll
    for (int o = 4; o <= 16; o <<= 1) {
        #pragma unroll
        for (int ni = 0; ni < 4; ni++) {
            p0[ni] += __shfl_xor_sync(0xffffffffu, p0[ni], o);
            p1[ni] += __shfl_xor_sync(0xffffffffu, p1[ni], o);
        }
    }
    if (c.lane < 4) {   // g == 0 lanes hold the full 64-row sums
        int wr2 = c.warp >> 2;
        size_t base = ((size_t)blockIdx.y * 2 + wr2) * FF;
        #pragma unroll
        for (int ni = 0; ni < 4; ni++) {
            int cn = c.bn + c.wc + ni * 8 + 2 * c.q;
            P[base + cn]     = p0[ni];
            P[base + cn + 1] = p1[ni];
        }
    }
}

// combine partials -> meanH[b][f] = (sum of 8 partials) / T   (fixed order)
__global__ void meanH_kernel(const float* __restrict__ P, float* __restrict__ meanH) {
    int f = blockIdx.x * blockDim.x + threadIdx.x;   // 0..FF-1
    int b = blockIdx.y;
    if (f >= FF) return;
    float s = 0.0f;
    #pragma unroll
    for (int j = 0; j < 8; j++)
        s += P[((size_t)(b * 4) * 2 + j) * FF + f];  // 4 m-tiles x 2 warp-rows, contiguous
    meanH[b * FF + f] = s * (1.0f / (float)TT);
}

// final: out[b][d] = mean_t res[b][t][d] + sum_f meanH[b][f] * fw2[f][d]  (fp32)
__global__ __launch_bounds__(128) void final_kernel(
        const float* __restrict__ res, const float* __restrict__ meanH,
        const float* __restrict__ fw2, float* __restrict__ out) {
    int d = blockIdx.x * blockDim.x + threadIdx.x;   // 0..DD-1
    int b = blockIdx.y;
    if (d >= DD) return;
    float s = 0.0f;
    const float* p = res + ((size_t)b * TT) * DD + d;
    for (int t = 0; t < TT; t++) s += p[(size_t)t * DD];
    s *= (1.0f / (float)TT);
    const float* mh = meanH + b * FF;
    float s2 = 0.0f;
    for (int f = 0; f < FF; f++) s2 = fmaf(mh[f], fw2[(size_t)f * DD + d], s2);
    out[b * DD + d] = s + s2;
}

// ---------------- kernel 3: tf32 flash attention + residual ----------------
#define SC 64
__global__ __launch_bounds__(256) void attn_mma_kernel(
        const float* __restrict__ qp, const float* __restrict__ kp,
        const float* __restrict__ vp, const float* __restrict__ qin,
        const int* __restrict__ qlens, const int* __restrict__ klens,
        float* __restrict__ res) {
    __shared__ uint32_t Ks[SC][68];
    __shared__ uint32_t Vs[SC][72];

    int b = blockIdx.z, h = blockIdx.y;
    int t0 = blockIdx.x * 128;
    int tid = threadIdx.x, lane = tid & 31, warp = tid >> 5;
    int g = lane >> 2, q = lane & 3;
    int klen = klens[b];
    int qlen = qlens[b];
    size_t base = ((size_t)b * TT) * DD + h * DHH;
    int rbase = t0 + warp * 16;

    float O[8][4];
    #pragma unroll
    for (int ni = 0; ni < 8; ni++)
        #pragma unroll
        for (int r = 0; r < 4; r++) O[ni][r] = 0.0f;
    float l0 = 0.0f, l1 = 0.0f;

    if (t0 < qlen) {
        uint32_t aQ[8][4];
        {
            const float* q0 = qp + base + (size_t)(rbase + g) * DD;
            const float* q8 = qp + base + (size_t)(rbase + g + 8) * DD;
            #pragma unroll
            for (int kk = 0; kk < 8; kk++) {
                int c = kk * 8 + q;
                aQ[kk][0] = f2tf32(q0[c] * 0.125f);
                aQ[kk][1] = f2tf32(q8[c] * 0.125f);
                aQ[kk][2] = f2tf32(q0[c + 4] * 0.125f);
                aQ[kk][3] = f2tf32(q8[c + 4] * 0.125f);
            }
        }

        float m0 = -1e30f, m1 = -1e30f;
        int nchunks = (klen + SC - 1) / SC;

        for (int ch = 0; ch < nchunks; ch++) {
            int s0 = ch * SC;
            __syncthreads();
            #pragma unroll
            for (int i = 0; i < 4; i++) {
                int c = tid + i * 256;
                int row = c >> 4;
                int col = (c & 15) * 4;
                size_t off = base + (size_t)(s0 + row) * DD + col;
                float4 kv4 = *(const float4*)(kp + off);
                Ks[row][col + 0] = __float_as_uint(kv4.x);
                Ks[row][col + 1] = __float_as_uint(kv4.y);
                Ks[row][col + 2] = __float_as_uint(kv4.z);
                Ks[row][col + 3] = __float_as_uint(kv4.w);
                float4 vv4 = *(const float4*)(vp + off);
                Vs[row][col + 0] = __float_as_uint(vv4.x);
                Vs[row][col + 1] = __float_as_uint(vv4.y);
                Vs[row][col + 2] = __float_as_uint(vv4.z);
                Vs[row][col + 3] = __float_as_uint(vv4.w);
            }
            __syncthreads();

            float sacc[8][4];
            #pragma unroll
            for (int ni = 0; ni < 8; ni++)
                #pragma unroll
                for (int r = 0; r < 4; r++) sacc[ni][r] = 0.0f;
            #pragma unroll
            for (int kk = 0; kk < 8; kk++) {
                #pragma unroll
                for (int ni = 0; ni < 8; ni++) {
                    uint32_t b0 = Ks[ni * 8 + g][kk * 8 + q];
                    uint32_t b1 = Ks[ni * 8 + g][kk * 8 + q + 4];
                    asm volatile(
                        "mma.sync.aligned.m16n8k8.row.col.f32.tf32.tf32.f32 "
                        "{%0,%1,%2,%3},{%4,%5,%6,%7},{%8,%9},{%0,%1,%2,%3};"
                        : "+f"(sacc[ni][0]), "+f"(sacc[ni][1]),
                          "+f"(sacc[ni][2]), "+f"(sacc[ni][3])
                        : "r"(aQ[kk][0]), "r"(aQ[kk][1]), "r"(aQ[kk][2]), "r"(aQ[kk][3]),
                          "r"(b0), "r"(b1));
                }
            }

            int cb = s0 + 2 * q;
            #pragma unroll
            for (int ni = 0; ni < 8; ni++) {
                if (cb + ni * 8     >= klen) { sacc[ni][0] = -1e30f; sacc[ni][2] = -1e30f; }
                if (cb + ni * 8 + 1 >= klen) { sacc[ni][1] = -1e30f; sacc[ni][3] = -1e30f; }
            }

            float mc0 = -1e30f, mc1 = -1e30f;
            #pragma unroll
            for (int ni = 0; ni < 8; ni++) {
                mc0 = fmaxf(mc0, fmaxf(sacc[ni][0], sacc[ni][1]));
                mc1 = fmaxf(mc1, fmaxf(sacc[ni][2], sacc[ni][3]));
            }
            #pragma unroll
            for (int o = 1; o <= 2; o <<= 1) {
                mc0 = fmaxf(mc0, __shfl_xor_sync(0xffffffffu, mc0, o));
                mc1 = fmaxf(mc1, __shfl_xor_sync(0xffffffffu, mc1, o));
            }
            float mn0 = fmaxf(m0, mc0), mn1 = fmaxf(m1, mc1);
            float al0 = __expf(m0 - mn0), al1 = __expf(m1 - mn1);
            m0 = mn0; m1 = mn1;

            float rs0 = 0.0f, rs1 = 0.0f;
            #pragma unroll
            for (int ni = 0; ni < 8; ni++) {
                float p0 = __expf(sacc[ni][0] - m0);
                float p1 = __expf(sacc[ni][1] - m0);
                float p2 = __expf(sacc[ni][2] - m1);
                float p3 = __expf(sacc[ni][3] - m1);
                rs0 += p0 + p1; rs1 += p2 + p3;
                sacc[ni][0] = p0; sacc[ni][1] = p1; sacc[ni][2] = p2; sacc[ni][3] = p3;
            }
            #pragma unroll
            for (int o = 1; o <= 2; o <<= 1) {
                rs0 += __shfl_xor_sync(0xffffffffu, rs0, o);
                rs1 += __shfl_xor_sync(0xffffffffu, rs1, o);
            }
            l0 = l0 * al0 + rs0;
            l1 = l1 * al1 + rs1;
            #pragma unroll
            for (int ni = 0; ni < 8; ni++) {
                O[ni][0] *= al0; O[ni][1] *= al0;
                O[ni][2] *= al1; O[ni][3] *= al1;
            }

            int srcA = g * 4 + (q >> 1);
            int srcB = srcA + 2;
            bool odd = (q & 1);
            #pragma unroll
            for (int ks = 0; ks < 8; ks++) {
                float v00 = __shfl_sync(0xffffffffu, sacc[ks][0], srcA);
                float v01 = __shfl_sync(0xffffffffu, sacc[ks][1], srcA);
                float v10 = __shfl_sync(0xffffffffu, sacc[ks][2], srcA);
                float v11 = __shfl_sync(0xffffffffu, sacc[ks][3], srcA);
                float w00 = __shfl_sync(0xffffffffu, sacc[ks][0], srcB);
                float w01 = __shfl_sync(0xffffffffu, sacc[ks][1], srcB);
                float w10 = __shfl_sync(0xffffffffu, sacc[ks][2], srcB);
                float w11 = __shfl_sync(0xffffffffu, sacc[ks][3], srcB);
                uint32_t a0 = f2tf32(odd ? v01 : v00);
                uint32_t a1 = f2tf32(odd ? v11 : v10);
                uint32_t a2 = f2tf32(odd ? w01 : w00);
                uint32_t a3 = f2tf32(odd ? w11 : w10);
                #pragma unroll
                for (int ni = 0; ni < 8; ni++) {
                    uint32_t b0 = Vs[ks * 8 + q    ][ni * 8 + g];
                    uint32_t b1 = Vs[ks * 8 + q + 4][ni * 8 + g];
                    asm volatile(
                        "mma.sync.aligned.m16n8k8.row.col.f32.tf32.tf32.f32 "
                        "{%0,%1,%2,%3},{%4,%5,%6,%7},{%8,%9},{%0,%1,%2,%3};"
                        : "+f"(O[ni][0]), "+f"(O[ni][1]),
                          "+f"(O[ni][2]), "+f"(O[ni][3])
                        : "r"(a0), "r"(a1), "r"(a2), "r"(a3),
                          "r"(b0), "r"(b1));
                }
            }
        }
    }

    // epilogue: res = tf32(qin + attn) (consumed by FFN1 mma + fp32 mean)
    float inv0 = (l0 > 0.0f) ? 1.0f / l0 : 0.0f;
    float inv1 = (l1 > 0.0f) ? 1.0f / l1 : 0.0f;
    int r0 = rbase + g, r1 = rbase + g + 8;
    float s0f = (r0 < qlen) ? inv0 : 0.0f;
    float s1f = (r1 < qlen) ? inv1 : 0.0f;
    size_t off0 = base + (size_t)r0 * DD + 2 * q;
    size_t off1 = base + (size_t)r1 * DD + 2 * q;
    #pragma unroll
    for (int ni = 0; ni < 8; ni++) {
        float2 i0 = *(const float2*)(qin + off0 + ni * 8);
        float2 i1 = *(const float2*)(qin + off1 + ni * 8);
        float2 o0 = make_float2(tf32r(i0.x + O[ni][0] * s0f), tf32r(i0.y + O[ni][1] * s0f));
        float2 o1 = make_float2(tf32r(i1.x + O[ni][2] * s1f), tf32r(i1.y + O[ni][3] * s1f));
        *(float2*)(res + off0 + ni * 8) = o0;
        *(float2*)(res + off1 + ni * 8) = o1;
    }
}

// ---------------- launch ----------------
extern "C" void kernel_launch(void* const* d_in, const int* in_sizes, int n_in,
                              void* d_out, int out_size) {
    const float* queries = (const float*)d_in[0];
    const float* keys    = (const float*)d_in[1];
    const int*   qlens   = (const int*)d_in[2];
    const int*   klens   = (const int*)d_in[3];
    const float* W_Q     = (const float*)d_in[4];
    const float* W_K     = (const float*)d_in[5];
    const float* W_V     = (const float*)d_in[6];
    const float* fw1     = (const float*)d_in[7];
    const float* fw2     = (const float*)d_in[8];
    float* out = (float*)d_out;

    float *qin, *kin, *qp, *kp, *vp, *resb, *part, *meanH;
    float *wq, *wk, *wv, *wkv, *f1;
    cudaGetSymbolAddress((void**)&qin,   g_qin);
    cudaGetSymbolAddress((void**)&kin,   g_kin);
    cudaGetSymbolAddress((void**)&qp,    g_qp);
    cudaGetSymbolAddress((void**)&kp,    g_kp);
    cudaGetSymbolAddress((void**)&vp,    g_vp);
    cudaGetSymbolAddress((void**)&resb,  g_res);
    cudaGetSymbolAddress((void**)&part,  g_part);
    cudaGetSymbolAddress((void**)&meanH, g_meanH);
    cudaGetSymbolAddress((void**)&wq,    g_wq);
    cudaGetSymbolAddress((void**)&wk,    g_wk);
    cudaGetSymbolAddress((void**)&wv,    g_wv);
    cudaGetSymbolAddress((void**)&wkv,   g_wkv);
    cudaGetSymbolAddress((void**)&f1,    g_f1);

    const int M = BB * TT;          // 32768
    const int n_elem = BB * TT * DD;
    const int GEMM_SMEM = 3 * GSTAGE * 4;  // 107520 B

    cudaFuncSetAttribute(tf32_gemm_k<true>,
                         cudaFuncAttributeMaxDynamicSharedMemorySize, GEMM_SMEM);
    cudaFuncSetAttribute(proj3_kernel,
                         cudaFuncAttributeMaxDynamicSharedMemorySize, GEMM_SMEM);
    cudaFuncSetAttribute(ffn1_reduce_kernel,
                         cudaFuncAttributeMaxDynamicSharedMemorySize, GEMM_SMEM);

    // 0. round weights to tf32
    roundw_all_kernel<<<(DD * FF + 255) / 256, 256>>>(
        W_Q, wq, W_K, wk, W_V, wv, fw1, f1);

    // 0b. fuse Wkv = Wk @ Wv
    tf32_gemm_k<true><<<dim3(DD / 128, DD / 128), 256, GEMM_SMEM>>>(
        wk, wv, wkv, DD, DD, DD);

    // 1. positional encoding
    addpe_kernel<<<(n_elem + 255) / 256, 256>>>(queries, keys, qin, kin);

    // 2. all three projections in one batched launch
    dim3 gproj(DD / 128, M / 128, 3);
    proj3_kernel<<<gproj, 256, GEMM_SMEM>>>(qin, kin, wq, wk, wkv, qp, kp, vp, M);

    // 3. attention + residual
    dim3 gattn(TT / 128, HH, BB);
    attn_mma_kernel<<<gattn, 256>>>(qp, kp, vp, qin, qlens, klens, resb);

    // 4. FFN1 with in-kernel row reduction (no hid store, no FFN2 GEMM)
    dim3 gff1(FF / 128, M / 128);
    ffn1_reduce_kernel<<<gff1, 256, GEMM_SMEM>>>(resb, f1, part, M);

    // 5. combine partials -> meanH
    dim3 gmh(FF / 256, BB);
    meanH_kernel<<<gmh, 256>>>(part, meanH);

    // 6. final: mean(res) + meanH @ fw2 (original fp32 fw2)
    dim3 gfin(DD / 128, BB);
    final_kernel<<<gfin, 128>>>(resb, meanH, fw2, out);
}